// round 1
// baseline (speedup 1.0000x reference)
#include <cuda_runtime.h>
#include <math.h>

#define NNODE 50000
#define DDIM  256
#define HH    8
#define DKK   32
#define EE    500000
#define QKVW  768
#define KDIM  256
#define ATT_SCALE 0.17677669529663687f  // 1/sqrt(32)

// ---------------- device scratch (static: no allocations allowed) ----------------
__device__ float g_Wcat[2][DDIM * QKVW];          // [Wq | Wk*w_att | Wv*w_msg]
__device__ float g_bcat[2][QKVW];
__device__ float g_QKV[2][(size_t)NNODE * QKVW];  // per node type: Q(256)|K'(256)|V'(256)
__device__ float g_hacc[2][(size_t)NNODE * DDIM]; // unnormalized sum_e w*v
__device__ float g_s[2][(size_t)NNODE * HH];      // sum_e w (per head)
__device__ float g_trans[2][(size_t)NNODE * DDIM];

// ---------------- 1. fold per-head matrices into the projection weights ----------
__global__ __launch_bounds__(256) void fold_kernel(
    const float* __restrict__ Wk, const float* __restrict__ bk,
    const float* __restrict__ Wq, const float* __restrict__ bq,
    const float* __restrict__ Wv, const float* __restrict__ bv,
    const float* __restrict__ w_att, const float* __restrict__ w_msg)
{
    int t = blockIdx.x >> 8;       // node type (== et for K/V fold, since st==et)
    int d = blockIdx.x & 255;      // input row
    int j = threadIdx.x;           // output col 0..255
    int h = j >> 5, jj = j & 31;

    const float* wkrow = Wk + ((size_t)t * 256 + d) * 256;
    const float* wvrow = Wv + ((size_t)t * 256 + d) * 256;
    const float* wa = w_att + ((size_t)(t * 8 + h)) * 1024 + jj;  // [i*32]
    const float* wm = w_msg + ((size_t)(t * 8 + h)) * 1024 + jj;

    float accK = 0.f, accV = 0.f;
    #pragma unroll 8
    for (int i = 0; i < 32; ++i) {
        accK += wkrow[h * 32 + i] * wa[i * 32];
        accV += wvrow[h * 32 + i] * wm[i * 32];
    }
    g_Wcat[t][(size_t)d * QKVW + j]       = Wq[((size_t)t * 256 + d) * 256 + j];
    g_Wcat[t][(size_t)d * QKVW + 256 + j] = accK;
    g_Wcat[t][(size_t)d * QKVW + 512 + j] = accV;

    if (d == 0) {
        float bK = 0.f, bV = 0.f;
        #pragma unroll 8
        for (int i = 0; i < 32; ++i) {
            bK += bk[t * 256 + h * 32 + i] * wa[i * 32];
            bV += bv[t * 256 + h * 32 + i] * wm[i * 32];
        }
        g_bcat[t][j]       = bq[t * 256 + j];
        g_bcat[t][256 + j] = bK;
        g_bcat[t][512 + j] = bV;
    }
}

// ---------------- 2. zero the accumulators (graph replays need this each call) ---
__global__ void zero_kernel()
{
    const long NH4 = 2L * NNODE * DDIM / 4;   // hacc float4 count
    const long NS4 = 2L * NNODE * HH / 4;     // s float4 count
    long i = (long)blockIdx.x * blockDim.x + threadIdx.x;
    float4 z = make_float4(0.f, 0.f, 0.f, 0.f);
    if (i < NH4) {
        ((float4*)g_hacc)[i] = z;
    } else if (i < NH4 + NS4) {
        ((float4*)g_s)[i - NH4] = z;
    }
}

// ---------------- 3. generic batched SGEMM: C = A(MxK) * B(KxN) + bias -----------
__global__ __launch_bounds__(256) void sgemm_bias_kernel(
    const float* __restrict__ A, long strideA,
    const float* __restrict__ B, long strideB,
    const float* __restrict__ bias, long strideBias,
    float* __restrict__ C, long strideC,
    int M, int Nn)
{
    const int t = blockIdx.z;
    A += (size_t)t * strideA; B += (size_t)t * strideB;
    bias += (size_t)t * strideBias; C += (size_t)t * strideC;

    __shared__ float As[8][128];
    __shared__ float Bs[8][128];

    const int tid = threadIdx.x;
    const int m0 = blockIdx.x * 128;
    const int n0 = blockIdx.y * 128;
    const int tx = tid & 15, ty = tid >> 4;

    const int arow = tid >> 1;
    const int acol = (tid & 1) * 4;
    const int brow = tid >> 5;
    const int bcol = (tid & 31) * 4;

    float acc[8][8];
    #pragma unroll
    for (int i = 0; i < 8; ++i)
        #pragma unroll
        for (int j = 0; j < 8; ++j) acc[i][j] = 0.f;

    for (int k0 = 0; k0 < KDIM; k0 += 8) {
        float4 a4 = make_float4(0.f, 0.f, 0.f, 0.f);
        int gr = m0 + arow;
        if (gr < M) a4 = *(const float4*)(A + (size_t)gr * KDIM + k0 + acol);
        As[acol + 0][arow] = a4.x;
        As[acol + 1][arow] = a4.y;
        As[acol + 2][arow] = a4.z;
        As[acol + 3][arow] = a4.w;

        float4 b4 = *(const float4*)(B + (size_t)(k0 + brow) * Nn + n0 + bcol);
        *(float4*)&Bs[brow][bcol] = b4;
        __syncthreads();

        #pragma unroll
        for (int kk = 0; kk < 8; ++kk) {
            float ra[8], rb[8];
            #pragma unroll
            for (int i = 0; i < 8; ++i) ra[i] = As[kk][ty * 8 + i];
            #pragma unroll
            for (int j = 0; j < 8; ++j) rb[j] = Bs[kk][tx * 8 + j];
            #pragma unroll
            for (int i = 0; i < 8; ++i)
                #pragma unroll
                for (int j = 0; j < 8; ++j)
                    acc[i][j] += ra[i] * rb[j];
        }
        __syncthreads();
    }

    #pragma unroll
    for (int i = 0; i < 8; ++i) {
        int gr = m0 + ty * 8 + i;
        if (gr >= M) continue;
        #pragma unroll
        for (int j = 0; j < 8; j += 4) {
            int gc = n0 + tx * 8 + j;
            float4 o;
            o.x = acc[i][j + 0] + bias[gc + 0];
            o.y = acc[i][j + 1] + bias[gc + 1];
            o.z = acc[i][j + 2] + bias[gc + 2];
            o.w = acc[i][j + 3] + bias[gc + 3];
            *(float4*)(C + (size_t)gr * Nn + gc) = o;
        }
    }
}

// ---------------- 4. single-pass edge kernel: scores, exp, weighted scatter ------
// One warp per edge. lane l: head h = l/4, covers elems (l%4)*8 .. +8 of that head.
// Conveniently base = l*8 == h*32 + (l%4)*8, which also equals this lane's message
// column range, so the same base indexes q/k dots AND v/hacc accumulation.
__global__ __launch_bounds__(256) void edge_kernel(
    const int* __restrict__ src, const int* __restrict__ dst,
    const float* __restrict__ mu)
{
    const int et = blockIdx.y;
    const int st = et, dt = 1 - et;
    const int warp = threadIdx.x >> 5;
    const long e = (long)blockIdx.x * 8 + warp;
    if (e >= EE) return;
    const int lane = threadIdx.x & 31;

    const int s_idx = src[(long)et * EE + e];
    const int d_idx = dst[(long)et * EE + e];

    const int h = lane >> 2;
    const int base = lane * 8;

    const float* qrow = g_QKV[dt] + (size_t)d_idx * QKVW;
    const float* krow = g_QKV[st] + (size_t)s_idx * QKVW + 256;
    const float* vrow = g_QKV[st] + (size_t)s_idx * QKVW + 512;

    float4 qa = *(const float4*)(qrow + base);
    float4 qb = *(const float4*)(qrow + base + 4);
    float4 ka = *(const float4*)(krow + base);
    float4 kb = *(const float4*)(krow + base + 4);

    float p = qa.x * ka.x + qa.y * ka.y + qa.z * ka.z + qa.w * ka.w
            + qb.x * kb.x + qb.y * kb.y + qb.z * kb.z + qb.w * kb.w;
    p += __shfl_xor_sync(0xffffffffu, p, 1);
    p += __shfl_xor_sync(0xffffffffu, p, 2);   // all 4 lanes of a head hold the dot

    float w = expf(p * mu[et * 8 + h] * ATT_SCALE);

    if ((lane & 3) == 0)
        atomicAdd(&g_s[dt][(size_t)d_idx * HH + h], w);

    float4 va = *(const float4*)(vrow + base);
    float4 vb = *(const float4*)(vrow + base + 4);
    float* hrow = g_hacc[dt] + (size_t)d_idx * DDIM + base;
    atomicAdd(hrow + 0, w * va.x);
    atomicAdd(hrow + 1, w * va.y);
    atomicAdd(hrow + 2, w * va.z);
    atomicAdd(hrow + 3, w * va.w);
    atomicAdd(hrow + 4, w * vb.x);
    atomicAdd(hrow + 5, w * vb.y);
    atomicAdd(hrow + 6, w * vb.z);
    atomicAdd(hrow + 7, w * vb.w);
}

// ---------------- 5. normalize: h = (s>0) ? hacc/s : 0 ---------------------------
__global__ void norm_kernel()
{
    const long TOT4 = 2L * NNODE * DDIM / 4;   // 6.4M float4
    long i = (long)blockIdx.x * blockDim.x + threadIdx.x;
    if (i >= TOT4) return;
    int c4 = (int)(i & 63);            // float4 index within row (4 floats -> same head)
    long node = i >> 6;                // combined t*NNODE + n
    float sv = ((const float*)g_s)[node * HH + (c4 >> 3)];
    float4 v = ((float4*)g_hacc)[i];
    if (sv > 0.f) {
        float inv = 1.f / sv;
        v.x *= inv; v.y *= inv; v.z *= inv; v.w *= inv;
    } else {
        v = make_float4(0.f, 0.f, 0.f, 0.f);
    }
    ((float4*)g_hacc)[i] = v;
}

// ---------------- 6. skip-mix + LayerNorm epilogue (warp per row) ---------------
__global__ __launch_bounds__(256) void ln_kernel(
    const float* __restrict__ feats, const float* __restrict__ skip,
    const float* __restrict__ ln_w, const float* __restrict__ ln_b,
    float* __restrict__ out)
{
    long row = (long)blockIdx.x * 8 + (threadIdx.x >> 5);  // 0 .. 2*NNODE-1
    const int lane = threadIdx.x & 31;
    const int t = (int)(row / NNODE);
    const float alpha = 1.f / (1.f + expf(-skip[t]));
    const float beta = 1.f - alpha;

    const float* tr = (const float*)g_trans + row * DDIM + lane * 8;
    const float* ft = feats + row * DDIM + lane * 8;

    float v[8];
    float4 t0 = *(const float4*)(tr);
    float4 t1 = *(const float4*)(tr + 4);
    float4 f0 = *(const float4*)(ft);
    float4 f1 = *(const float4*)(ft + 4);
    v[0] = alpha * t0.x + beta * f0.x;  v[1] = alpha * t0.y + beta * f0.y;
    v[2] = alpha * t0.z + beta * f0.z;  v[3] = alpha * t0.w + beta * f0.w;
    v[4] = alpha * t1.x + beta * f1.x;  v[5] = alpha * t1.y + beta * f1.y;
    v[6] = alpha * t1.z + beta * f1.z;  v[7] = alpha * t1.w + beta * f1.w;

    float sum = 0.f, sq = 0.f;
    #pragma unroll
    for (int j = 0; j < 8; ++j) { sum += v[j]; sq += v[j] * v[j]; }
    #pragma unroll
    for (int o = 16; o > 0; o >>= 1) {
        sum += __shfl_xor_sync(0xffffffffu, sum, o);
        sq  += __shfl_xor_sync(0xffffffffu, sq, o);
    }
    const float mean = sum * (1.f / 256.f);
    const float var  = sq * (1.f / 256.f) - mean * mean;
    const float rstd = rsqrtf(var + 1e-5f);

    const int cbase = t * 256 + lane * 8;
    float* op = out + row * DDIM + lane * 8;
    float4 o0, o1;
    o0.x = (v[0] - mean) * rstd * ln_w[cbase + 0] + ln_b[cbase + 0];
    o0.y = (v[1] - mean) * rstd * ln_w[cbase + 1] + ln_b[cbase + 1];
    o0.z = (v[2] - mean) * rstd * ln_w[cbase + 2] + ln_b[cbase + 2];
    o0.w = (v[3] - mean) * rstd * ln_w[cbase + 3] + ln_b[cbase + 3];
    o1.x = (v[4] - mean) * rstd * ln_w[cbase + 4] + ln_b[cbase + 4];
    o1.y = (v[5] - mean) * rstd * ln_w[cbase + 5] + ln_b[cbase + 5];
    o1.z = (v[6] - mean) * rstd * ln_w[cbase + 6] + ln_b[cbase + 6];
    o1.w = (v[7] - mean) * rstd * ln_w[cbase + 7] + ln_b[cbase + 7];
    *(float4*)(op)     = o0;
    *(float4*)(op + 4) = o1;
}

// ---------------- host launch -----------------------------------------------------
extern "C" void kernel_launch(void* const* d_in, const int* in_sizes, int n_in,
                              void* d_out, int out_size)
{
    const float* feats = (const float*)d_in[0];
    const float* Wk    = (const float*)d_in[1];
    const float* bk    = (const float*)d_in[2];
    const float* Wq    = (const float*)d_in[3];
    const float* bq    = (const float*)d_in[4];
    const float* Wv    = (const float*)d_in[5];
    const float* bv    = (const float*)d_in[6];
    const float* Wa    = (const float*)d_in[7];
    const float* ba    = (const float*)d_in[8];
    const float* ln_w  = (const float*)d_in[9];
    const float* ln_b  = (const float*)d_in[10];
    const float* skip  = (const float*)d_in[11];
    const float* mu    = (const float*)d_in[12];
    const float* w_att = (const float*)d_in[13];
    const float* w_msg = (const float*)d_in[14];
    const int*   src   = (const int*)d_in[15];
    const int*   dst   = (const int*)d_in[16];
    float* out = (float*)d_out;

    float *pWcat, *pbcat, *pQKV, *phacc, *ptrans;
    cudaGetSymbolAddress((void**)&pWcat, g_Wcat);
    cudaGetSymbolAddress((void**)&pbcat, g_bcat);
    cudaGetSymbolAddress((void**)&pQKV, g_QKV);
    cudaGetSymbolAddress((void**)&phacc, g_hacc);
    cudaGetSymbolAddress((void**)&ptrans, g_trans);

    // 1. fold weights
    fold_kernel<<<512, 256>>>(Wk, bk, Wq, bq, Wv, bv, w_att, w_msg);

    // 2. zero accumulators
    {
        const long tot4 = 2L * NNODE * DDIM / 4 + 2L * NNODE * HH / 4;
        int blocks = (int)((tot4 + 255) / 256);
        zero_kernel<<<blocks, 256>>>();
    }

    // 3. QKV projection: (2) x [50000x256] @ [256x768] + bias
    {
        dim3 grid((NNODE + 127) / 128, QKVW / 128, 2);
        sgemm_bias_kernel<<<grid, 256>>>(
            feats, (long)NNODE * DDIM,
            pWcat, (long)DDIM * QKVW,
            pbcat, (long)QKVW,
            pQKV, (long)NNODE * QKVW,
            NNODE, QKVW);
    }

    // 4. edge pass (both edge types in parallel; disjoint dst node types)
    {
        dim3 grid((EE + 7) / 8, 2);
        edge_kernel<<<grid, 256>>>(src, dst, mu);
    }

    // 5. normalize softmax denominators
    {
        const long tot4 = 2L * NNODE * DDIM / 4;
        int blocks = (int)((tot4 + 255) / 256);
        norm_kernel<<<blocks, 256>>>();
    }

    // 6. output projection: (2) x [50000x256] @ [256x256] + ba
    {
        dim3 grid((NNODE + 127) / 128, DDIM / 128, 2);
        sgemm_bias_kernel<<<grid, 256>>>(
            phacc, (long)NNODE * DDIM,
            Wa, (long)DDIM * DDIM,
            ba, (long)DDIM,
            ptrans, (long)NNODE * DDIM,
            NNODE, DDIM);
    }

    // 7. skip-mix + LayerNorm -> d_out
    ln_kernel<<<(2 * NNODE) / 8, 256>>>(feats, skip, ln_w, ln_b, out);
}

// round 3
// speedup vs baseline: 1.3716x; 1.3716x over previous
#include <cuda_runtime.h>
#include <cuda_bf16.h>
#include <math.h>
#include <stdint.h>

#define NNODE 50000
#define DDIM  256
#define HH    8
#define EE    500000
#define QKVW  768
#define ATT_SCALE 0.17677669529663687f  // 1/sqrt(32)

// ======================= device scratch ==========================================
__device__ float g_bcat[2][QKVW];
__device__ __nv_bfloat16 g_WcatT_hi[2][(size_t)QKVW * DDIM];  // [n][k], n = Q|K'|V'
__device__ __nv_bfloat16 g_WcatT_lo[2][(size_t)QKVW * DDIM];
__device__ __nv_bfloat16 g_WaT_hi[2][(size_t)DDIM * DDIM];
__device__ __nv_bfloat16 g_WaT_lo[2][(size_t)DDIM * DDIM];
__device__ __nv_bfloat16 g_fbf_hi[2][(size_t)NNODE * DDIM];
__device__ __nv_bfloat16 g_fbf_lo[2][(size_t)NNODE * DDIM];
__device__ __nv_bfloat16 g_hbf_hi[2][(size_t)NNODE * DDIM];
__device__ __nv_bfloat16 g_hbf_lo[2][(size_t)NNODE * DDIM];
__device__ float g_QKV[2][(size_t)NNODE * QKVW];  // fp32: Q(256)|K'(256)|V'(256)
__device__ float g_hacc[2][(size_t)NNODE * DDIM];
__device__ float g_s[2][(size_t)NNODE * HH];
__device__ float g_trans[2][(size_t)NNODE * DDIM];

// ======================= PTX helpers (base-target safe) ==========================
__device__ __forceinline__ uint32_t smem_u32(const void* p) {
    uint32_t a;
    asm("{ .reg .u64 t; cvta.to.shared.u64 t, %1; cvt.u32.u64 %0, t; }" : "=r"(a) : "l"(p));
    return a;
}
__device__ __forceinline__ void ldm_x4(uint32_t* r, uint32_t addr) {
    asm volatile("ldmatrix.sync.aligned.m8n8.x4.shared.b16 {%0,%1,%2,%3}, [%4];"
                 : "=r"(r[0]), "=r"(r[1]), "=r"(r[2]), "=r"(r[3]) : "r"(addr));
}
__device__ __forceinline__ void ldm_x2(uint32_t* r, uint32_t addr) {
    asm volatile("ldmatrix.sync.aligned.m8n8.x2.shared.b16 {%0,%1}, [%2];"
                 : "=r"(r[0]), "=r"(r[1]) : "r"(addr));
}
__device__ __forceinline__ void mma_bf16(float* c, const uint32_t* a, const uint32_t* b) {
    asm volatile("mma.sync.aligned.m16n8k16.row.col.f32.bf16.bf16.f32 "
                 "{%0,%1,%2,%3}, {%4,%5,%6,%7}, {%8,%9}, {%0,%1,%2,%3};"
                 : "+f"(c[0]), "+f"(c[1]), "+f"(c[2]), "+f"(c[3])
                 : "r"(a[0]), "r"(a[1]), "r"(a[2]), "r"(a[3]), "r"(b[0]), "r"(b[1]));
}

// ======================= 1. prep: fold + transpose + bf16 split ==================
__global__ __launch_bounds__(256) void prep_kernel(
    const float* __restrict__ Wk, const float* __restrict__ bk,
    const float* __restrict__ Wq, const float* __restrict__ bq,
    const float* __restrict__ Wv, const float* __restrict__ bv,
    const float* __restrict__ Wa,
    const float* __restrict__ w_att, const float* __restrict__ w_msg)
{
    const int t = blockIdx.y;
    const int n = blockIdx.x;     // 0..1023: 0..767 -> WcatT, 768..1023 -> WaT
    const int k = threadIdx.x;    // input dim 0..255

    float val;
    if (n < 768) {
        if (n < 256) {
            val = Wq[((size_t)t * 256 + k) * 256 + n];
        } else {
            const int j = (n - 256) & 255;
            const int h = j >> 5, jj = j & 31;
            const float* W = (n < 512) ? Wk : Wv;
            const float* wm = ((n < 512) ? w_att : w_msg) + ((size_t)(t * 8 + h)) * 1024 + jj;
            const float* wrow = W + ((size_t)t * 256 + k) * 256 + h * 32;
            float a = 0.f;
            #pragma unroll 8
            for (int i = 0; i < 32; ++i) a += wrow[i] * wm[i * 32];
            val = a;
        }
        __nv_bfloat16 hi = __float2bfloat16(val);
        __nv_bfloat16 lo = __float2bfloat16(val - __bfloat162float(hi));
        g_WcatT_hi[t][(size_t)n * 256 + k] = hi;
        g_WcatT_lo[t][(size_t)n * 256 + k] = lo;
        if (k == 0) {
            float b;
            if (n < 256) b = bq[t * 256 + n];
            else {
                const int j = (n - 256) & 255;
                const int h = j >> 5, jj = j & 31;
                const float* bb = (n < 512) ? bk : bv;
                const float* wm = ((n < 512) ? w_att : w_msg) + ((size_t)(t * 8 + h)) * 1024 + jj;
                float a = 0.f;
                #pragma unroll 8
                for (int i = 0; i < 32; ++i) a += bb[t * 256 + h * 32 + i] * wm[i * 32];
                b = a;
            }
            g_bcat[t][n] = b;
        }
    } else {
        const int nn = n - 768;
        val = Wa[((size_t)t * 256 + k) * 256 + nn];
        __nv_bfloat16 hi = __float2bfloat16(val);
        __nv_bfloat16 lo = __float2bfloat16(val - __bfloat162float(hi));
        g_WaT_hi[t][(size_t)nn * 256 + k] = hi;
        g_WaT_lo[t][(size_t)nn * 256 + k] = lo;
    }
}

// ======================= 2. fp32 -> bf16 hi/lo split =============================
__global__ void convsplit_kernel(const float* __restrict__ src,
                                 __nv_bfloat16* __restrict__ hi,
                                 __nv_bfloat16* __restrict__ lo, long n4)
{
    long i = (long)blockIdx.x * blockDim.x + threadIdx.x;
    if (i >= n4) return;
    float4 v = ((const float4*)src)[i];
    __nv_bfloat16 h0 = __float2bfloat16(v.x), h1 = __float2bfloat16(v.y);
    __nv_bfloat16 h2 = __float2bfloat16(v.z), h3 = __float2bfloat16(v.w);
    __nv_bfloat16 l0 = __float2bfloat16(v.x - __bfloat162float(h0));
    __nv_bfloat16 l1 = __float2bfloat16(v.y - __bfloat162float(h1));
    __nv_bfloat16 l2 = __float2bfloat16(v.z - __bfloat162float(h2));
    __nv_bfloat16 l3 = __float2bfloat16(v.w - __bfloat162float(h3));
    ((__nv_bfloat162*)hi)[i * 2]     = __halves2bfloat162(h0, h1);
    ((__nv_bfloat162*)hi)[i * 2 + 1] = __halves2bfloat162(h2, h3);
    ((__nv_bfloat162*)lo)[i * 2]     = __halves2bfloat162(l0, l1);
    ((__nv_bfloat162*)lo)[i * 2 + 1] = __halves2bfloat162(l2, l3);
}

// ======================= 3. zero accumulators ====================================
__global__ void zero_kernel()
{
    const long NH4 = 2L * NNODE * DDIM / 4;
    const long NS4 = 2L * NNODE * HH / 4;
    long i = (long)blockIdx.x * blockDim.x + threadIdx.x;
    float4 z = make_float4(0.f, 0.f, 0.f, 0.f);
    if (i < NH4) ((float4*)g_hacc)[i] = z;
    else if (i < NH4 + NS4) ((float4*)g_s)[i - NH4] = z;
}

// ======================= 4. split-bf16 HMMA GEMM =================================
// C[M, Ntot](fp32) = A[M,256] * B[Ntot,256]^T + bias, per type (blockIdx.z).
// A,B as bf16 hi/lo. 3 passes (hh, hl, lh) into the same fp32 accumulators.
// Block: 256 thr (8 warps), tile 128x128, BK=64. Warp tile 64x32.
#define BM 128
#define BN 128
#define BK 64
#define LDS_STRIDE 72          // bf16 elems per smem row (64 + 8 pad)
#define AS_HI 0
#define AS_LO (AS_HI + BM * LDS_STRIDE * 2)
#define BS_HI (AS_LO + BM * LDS_STRIDE * 2)
#define BS_LO (BS_HI + BN * LDS_STRIDE * 2)
#define GEMM_SMEM (BS_LO + BN * LDS_STRIDE * 2)   // 73728 bytes

__global__ __launch_bounds__(256) void hmma_gemm_kernel(
    const __nv_bfloat16* __restrict__ Ahi, const __nv_bfloat16* __restrict__ Alo, long strideA,
    const __nv_bfloat16* __restrict__ Bhi, const __nv_bfloat16* __restrict__ Blo, long strideB,
    const float* __restrict__ bias, long strideBias,
    float* __restrict__ C, long strideC,
    int M, int Ntot)
{
    extern __shared__ char smem[];
    const uint32_t sbase = smem_u32(smem);

    const int tid = threadIdx.x;
    const int wid = tid >> 5, lane = tid & 31;
    const int t = blockIdx.z;
    const int m0 = blockIdx.x * BM;
    const int n0 = blockIdx.y * BN;
    const int mw = (wid & 1) * 64;        // warp m offset in tile
    const int nw = (wid >> 1) * 32;       // warp n offset in tile

    Ahi += (size_t)t * strideA;  Alo += (size_t)t * strideA;
    Bhi += (size_t)t * strideB;  Blo += (size_t)t * strideB;
    bias += (size_t)t * strideBias;
    C += (size_t)t * strideC;

    float acc[4][4][4];
    #pragma unroll
    for (int i = 0; i < 4; ++i)
        #pragma unroll
        for (int j = 0; j < 4; ++j)
            #pragma unroll
            for (int r = 0; r < 4; ++r) acc[i][j][r] = 0.f;

    for (int kofs = 0; kofs < 256; kofs += BK) {
        __syncthreads();
        // ---- load A tile (128 x 64 hi & lo) ----
        #pragma unroll
        for (int i = 0; i < 4; ++i) {
            int idx = tid + i * 256;                 // 0..1023
            int row = idx >> 3, c = (idx & 7) * 8;   // c: bf16 elem offset
            uint32_t soff = (uint32_t)(row * LDS_STRIDE + c) * 2;
            uint4 vh = make_uint4(0, 0, 0, 0), vl = make_uint4(0, 0, 0, 0);
            int gr = m0 + row;
            if (gr < M) {
                size_t s = (size_t)gr * 256 + kofs + c;
                vh = *(const uint4*)(Ahi + s);
                vl = *(const uint4*)(Alo + s);
            }
            *(uint4*)(smem + AS_HI + soff) = vh;
            *(uint4*)(smem + AS_LO + soff) = vl;
        }
        // ---- load B tile (128 x 64 hi & lo) ----
        #pragma unroll
        for (int i = 0; i < 4; ++i) {
            int idx = tid + i * 256;
            int row = idx >> 3, c = (idx & 7) * 8;
            uint32_t soff = (uint32_t)(row * LDS_STRIDE + c) * 2;
            size_t s = (size_t)(n0 + row) * 256 + kofs + c;
            *(uint4*)(smem + BS_HI + soff) = *(const uint4*)(Bhi + s);
            *(uint4*)(smem + BS_LO + soff) = *(const uint4*)(Blo + s);
        }
        __syncthreads();

        #pragma unroll
        for (int kk = 0; kk < BK / 16; ++kk) {
            uint32_t a_hi[4][4], a_lo[4][4], b_hi[4][2], b_lo[4][2];
            // A fragments: 4 m16 tiles
            #pragma unroll
            for (int i = 0; i < 4; ++i) {
                uint32_t off = (uint32_t)((mw + i * 16 + (lane & 15)) * LDS_STRIDE
                                          + kk * 16 + (lane >> 4) * 8) * 2;
                ldm_x4(a_hi[i], sbase + AS_HI + off);
                ldm_x4(a_lo[i], sbase + AS_LO + off);
            }
            // B fragments: 4 n8 tiles (B is [n][k] = col-major -> non-trans ldmatrix)
            #pragma unroll
            for (int j = 0; j < 4; ++j) {
                uint32_t off = (uint32_t)((nw + j * 8 + (lane & 7)) * LDS_STRIDE
                                          + kk * 16 + ((lane >> 3) & 1) * 8) * 2;
                ldm_x2(b_hi[j], sbase + BS_HI + off);
                ldm_x2(b_lo[j], sbase + BS_LO + off);
            }
            #pragma unroll
            for (int i = 0; i < 4; ++i)
                #pragma unroll
                for (int j = 0; j < 4; ++j) {
                    mma_bf16(acc[i][j], a_hi[i], b_hi[j]);
                    mma_bf16(acc[i][j], a_hi[i], b_lo[j]);
                    mma_bf16(acc[i][j], a_lo[i], b_hi[j]);
                }
        }
    }

    // ---- epilogue: acc + bias -> C ----
    #pragma unroll
    for (int i = 0; i < 4; ++i) {
        int r0 = m0 + mw + i * 16 + (lane >> 2);
        int r1 = r0 + 8;
        #pragma unroll
        for (int j = 0; j < 4; ++j) {
            int col = n0 + nw + j * 8 + (lane & 3) * 2;
            float b0 = bias[col], b1 = bias[col + 1];
            if (r0 < M) {
                float2 o = make_float2(acc[i][j][0] + b0, acc[i][j][1] + b1);
                *(float2*)(C + (size_t)r0 * Ntot + col) = o;
            }
            if (r1 < M) {
                float2 o = make_float2(acc[i][j][2] + b0, acc[i][j][3] + b1);
                *(float2*)(C + (size_t)r1 * Ntot + col) = o;
            }
        }
    }
}

// ======================= 5. single-pass edge kernel ==============================
__global__ __launch_bounds__(256) void edge_kernel(
    const int* __restrict__ src, const int* __restrict__ dst,
    const float* __restrict__ mu)
{
    const int et = blockIdx.y;
    const int st = et, dt = 1 - et;
    const int warp = threadIdx.x >> 5;
    const long e = (long)blockIdx.x * 8 + warp;
    if (e >= EE) return;
    const int lane = threadIdx.x & 31;

    const int s_idx = src[(long)et * EE + e];
    const int d_idx = dst[(long)et * EE + e];

    const int h = lane >> 2;
    const int base = lane * 8;

    const float* qrow = g_QKV[dt] + (size_t)d_idx * QKVW;
    const float* krow = g_QKV[st] + (size_t)s_idx * QKVW + 256;
    const float* vrow = g_QKV[st] + (size_t)s_idx * QKVW + 512;

    float4 qa = *(const float4*)(qrow + base);
    float4 qb = *(const float4*)(qrow + base + 4);
    float4 ka = *(const float4*)(krow + base);
    float4 kb = *(const float4*)(krow + base + 4);

    float p = qa.x * ka.x + qa.y * ka.y + qa.z * ka.z + qa.w * ka.w
            + qb.x * kb.x + qb.y * kb.y + qb.z * kb.z + qb.w * kb.w;
    p += __shfl_xor_sync(0xffffffffu, p, 1);
    p += __shfl_xor_sync(0xffffffffu, p, 2);

    float w = expf(p * mu[et * 8 + h] * ATT_SCALE);

    if ((lane & 3) == 0)
        atomicAdd(&g_s[dt][(size_t)d_idx * HH + h], w);

    float4 va = *(const float4*)(vrow + base);
    float4 vb = *(const float4*)(vrow + base + 4);
    float* hrow = g_hacc[dt] + (size_t)d_idx * DDIM + base;
    atomicAdd(hrow + 0, w * va.x);
    atomicAdd(hrow + 1, w * va.y);
    atomicAdd(hrow + 2, w * va.z);
    atomicAdd(hrow + 3, w * va.w);
    atomicAdd(hrow + 4, w * vb.x);
    atomicAdd(hrow + 5, w * vb.y);
    atomicAdd(hrow + 6, w * vb.z);
    atomicAdd(hrow + 7, w * vb.w);
}

// ======================= 6. normalize + bf16 split for GEMM2 =====================
__global__ void norm_kernel()
{
    const long TOT4 = 2L * NNODE * DDIM / 4;
    long i = (long)blockIdx.x * blockDim.x + threadIdx.x;
    if (i >= TOT4) return;
    int c4 = (int)(i & 63);
    long node = i >> 6;
    float sv = ((const float*)g_s)[node * HH + (c4 >> 3)];
    float4 v = ((float4*)g_hacc)[i];
    if (sv > 0.f) {
        float inv = 1.f / sv;
        v.x *= inv; v.y *= inv; v.z *= inv; v.w *= inv;
    } else {
        v = make_float4(0.f, 0.f, 0.f, 0.f);
    }
    __nv_bfloat16 h0 = __float2bfloat16(v.x), h1 = __float2bfloat16(v.y);
    __nv_bfloat16 h2 = __float2bfloat16(v.z), h3 = __float2bfloat16(v.w);
    __nv_bfloat16 l0 = __float2bfloat16(v.x - __bfloat162float(h0));
    __nv_bfloat16 l1 = __float2bfloat16(v.y - __bfloat162float(h1));
    __nv_bfloat16 l2 = __float2bfloat16(v.z - __bfloat162float(h2));
    __nv_bfloat16 l3 = __float2bfloat16(v.w - __bfloat162float(h3));
    ((__nv_bfloat162*)g_hbf_hi)[i * 2]     = __halves2bfloat162(h0, h1);
    ((__nv_bfloat162*)g_hbf_hi)[i * 2 + 1] = __halves2bfloat162(h2, h3);
    ((__nv_bfloat162*)g_hbf_lo)[i * 2]     = __halves2bfloat162(l0, l1);
    ((__nv_bfloat162*)g_hbf_lo)[i * 2 + 1] = __halves2bfloat162(l2, l3);
}

// ======================= 7. skip-mix + LayerNorm =================================
__global__ __launch_bounds__(256) void ln_kernel(
    const float* __restrict__ feats, const float* __restrict__ skip,
    const float* __restrict__ ln_w, const float* __restrict__ ln_b,
    float* __restrict__ out)
{
    long row = (long)blockIdx.x * 8 + (threadIdx.x >> 5);
    const int lane = threadIdx.x & 31;
    const int t = (int)(row / NNODE);
    const float alpha = 1.f / (1.f + expf(-skip[t]));
    const float beta = 1.f - alpha;

    const float* tr = (const float*)g_trans + row * DDIM + lane * 8;
    const float* ft = feats + row * DDIM + lane * 8;

    float v[8];
    float4 t0 = *(const float4*)(tr);
    float4 t1 = *(const float4*)(tr + 4);
    float4 f0 = *(const float4*)(ft);
    float4 f1 = *(const float4*)(ft + 4);
    v[0] = alpha * t0.x + beta * f0.x;  v[1] = alpha * t0.y + beta * f0.y;
    v[2] = alpha * t0.z + beta * f0.z;  v[3] = alpha * t0.w + beta * f0.w;
    v[4] = alpha * t1.x + beta * f1.x;  v[5] = alpha * t1.y + beta * f1.y;
    v[6] = alpha * t1.z + beta * f1.z;  v[7] = alpha * t1.w + beta * f1.w;

    float sum = 0.f, sq = 0.f;
    #pragma unroll
    for (int j = 0; j < 8; ++j) { sum += v[j]; sq += v[j] * v[j]; }
    #pragma unroll
    for (int o = 16; o > 0; o >>= 1) {
        sum += __shfl_xor_sync(0xffffffffu, sum, o);
        sq  += __shfl_xor_sync(0xffffffffu, sq, o);
    }
    const float mean = sum * (1.f / 256.f);
    const float var  = sq * (1.f / 256.f) - mean * mean;
    const float rstd = rsqrtf(var + 1e-5f);

    const int cbase = t * 256 + lane * 8;
    float* op = out + row * DDIM + lane * 8;
    float4 o0, o1;
    o0.x = (v[0] - mean) * rstd * ln_w[cbase + 0] + ln_b[cbase + 0];
    o0.y = (v[1] - mean) * rstd * ln_w[cbase + 1] + ln_b[cbase + 1];
    o0.z = (v[2] - mean) * rstd * ln_w[cbase + 2] + ln_b[cbase + 2];
    o0.w = (v[3] - mean) * rstd * ln_w[cbase + 3] + ln_b[cbase + 3];
    o1.x = (v[4] - mean) * rstd * ln_w[cbase + 4] + ln_b[cbase + 4];
    o1.y = (v[5] - mean) * rstd * ln_w[cbase + 5] + ln_b[cbase + 5];
    o1.z = (v[6] - mean) * rstd * ln_w[cbase + 6] + ln_b[cbase + 6];
    o1.w = (v[7] - mean) * rstd * ln_w[cbase + 7] + ln_b[cbase + 7];
    *(float4*)(op)     = o0;
    *(float4*)(op + 4) = o1;
}

// ======================= host launch =============================================
extern "C" void kernel_launch(void* const* d_in, const int* in_sizes, int n_in,
                              void* d_out, int out_size)
{
    const float* feats = (const float*)d_in[0];
    const float* Wk    = (const float*)d_in[1];
    const float* bk    = (const float*)d_in[2];
    const float* Wq    = (const float*)d_in[3];
    const float* bq    = (const float*)d_in[4];
    const float* Wv    = (const float*)d_in[5];
    const float* bv    = (const float*)d_in[6];
    const float* Wa    = (const float*)d_in[7];
    const float* ba    = (const float*)d_in[8];
    const float* ln_w  = (const float*)d_in[9];
    const float* ln_b  = (const float*)d_in[10];
    const float* skip  = (const float*)d_in[11];
    const float* mu    = (const float*)d_in[12];
    const float* w_att = (const float*)d_in[13];
    const float* w_msg = (const float*)d_in[14];
    const int*   src   = (const int*)d_in[15];
    const int*   dst   = (const int*)d_in[16];
    float* out = (float*)d_out;

    static bool attr_done = false;
    if (!attr_done) {
        cudaFuncSetAttribute(hmma_gemm_kernel,
                             cudaFuncAttributeMaxDynamicSharedMemorySize, GEMM_SMEM);
        attr_done = true;
    }

    float *pbcat, *pQKV, *phacc, *ptrans;
    __nv_bfloat16 *pWcH, *pWcL, *pWaH, *pWaL, *pfH, *pfL, *phH, *phL;
    cudaGetSymbolAddress((void**)&pbcat, g_bcat);
    cudaGetSymbolAddress((void**)&pQKV, g_QKV);
    cudaGetSymbolAddress((void**)&phacc, g_hacc);
    cudaGetSymbolAddress((void**)&ptrans, g_trans);
    cudaGetSymbolAddress((void**)&pWcH, g_WcatT_hi);
    cudaGetSymbolAddress((void**)&pWcL, g_WcatT_lo);
    cudaGetSymbolAddress((void**)&pWaH, g_WaT_hi);
    cudaGetSymbolAddress((void**)&pWaL, g_WaT_lo);
    cudaGetSymbolAddress((void**)&pfH, g_fbf_hi);
    cudaGetSymbolAddress((void**)&pfL, g_fbf_lo);
    cudaGetSymbolAddress((void**)&phH, g_hbf_hi);
    cudaGetSymbolAddress((void**)&phL, g_hbf_lo);

    // 1. weight prep (fold + transpose + bf16 split)
    {
        dim3 grid(1024, 2);
        prep_kernel<<<grid, 256>>>(Wk, bk, Wq, bq, Wv, bv, Wa, w_att, w_msg);
    }

    // 2. feats -> bf16 hi/lo
    {
        const long n4 = 2L * NNODE * DDIM / 4;
        convsplit_kernel<<<(int)((n4 + 255) / 256), 256>>>(feats, pfH, pfL, n4);
    }

    // 3. zero accumulators
    {
        const long tot4 = 2L * NNODE * DDIM / 4 + 2L * NNODE * HH / 4;
        zero_kernel<<<(int)((tot4 + 255) / 256), 256>>>();
    }

    // 4. QKV projection: (2) x [50000 x 256] @ [256 x 768] + bcat  (HMMA)
    {
        dim3 grid((NNODE + BM - 1) / BM, QKVW / BN, 2);
        hmma_gemm_kernel<<<grid, 256, GEMM_SMEM>>>(
            pfH, pfL, (long)NNODE * DDIM,
            pWcH, pWcL, (long)QKVW * DDIM,
            pbcat, (long)QKVW,
            pQKV, (long)NNODE * QKVW,
            NNODE, QKVW);
    }

    // 5. edge pass
    {
        dim3 grid((EE + 7) / 8, 2);
        edge_kernel<<<grid, 256>>>(src, dst, mu);
    }

    // 6. softmax normalize + bf16 split
    {
        const long tot4 = 2L * NNODE * DDIM / 4;
        norm_kernel<<<(int)((tot4 + 255) / 256), 256>>>();
    }

    // 7. output projection: (2) x [50000 x 256] @ [256 x 256] + ba  (HMMA)
    {
        dim3 grid((NNODE + BM - 1) / BM, DDIM / BN, 2);
        hmma_gemm_kernel<<<grid, 256, GEMM_SMEM>>>(
            phH, phL, (long)NNODE * DDIM,
            pWaH, pWaL, (long)DDIM * DDIM,
            ba, (long)DDIM,
            ptrans, (long)NNODE * DDIM,
            NNODE, DDIM);
    }

    // 8. skip-mix + LayerNorm -> d_out
    ln_kernel<<<(2 * NNODE) / 8, 256>>>(feats, skip, ln_w, ln_b, out);
}

// round 4
// speedup vs baseline: 3.1077x; 2.2657x over previous
#include <cuda_runtime.h>
#include <cuda_bf16.h>
#include <math.h>
#include <stdint.h>

#define NNODE 50000
#define DDIM  256
#define HH    8
#define EE    500000
#define QKVW  768
#define ATT_SCALE 0.17677669529663687f  // 1/sqrt(32)

// ======================= device scratch ==========================================
__device__ float g_bcat[2][QKVW];
__device__ __nv_bfloat16 g_WcatT_hi[2][(size_t)QKVW * DDIM];  // [n][k], n = Q|K'|V'
__device__ __nv_bfloat16 g_WcatT_lo[2][(size_t)QKVW * DDIM];
__device__ __nv_bfloat16 g_WaT_hi[2][(size_t)DDIM * DDIM];
__device__ __nv_bfloat16 g_WaT_lo[2][(size_t)DDIM * DDIM];
__device__ __nv_bfloat16 g_fbf_hi[2][(size_t)NNODE * DDIM];
__device__ __nv_bfloat16 g_fbf_lo[2][(size_t)NNODE * DDIM];
__device__ __nv_bfloat16 g_hbf_hi[2][(size_t)NNODE * DDIM];
__device__ __nv_bfloat16 g_hbf_lo[2][(size_t)NNODE * DDIM];
__device__ float g_QKV[2][(size_t)NNODE * QKVW];  // fp32: Q(256)|K'(256)|V'(256)
__device__ float g_trans[2][(size_t)NNODE * DDIM];
// CSR-by-destination scratch
__device__ int g_deg[2][NNODE];
__device__ int g_rows[2][NNODE + 1];
__device__ int g_cursor[2][NNODE];
__device__ int g_esrc[2][EE];

// ======================= PTX helpers (base-target safe) ==========================
__device__ __forceinline__ uint32_t smem_u32(const void* p) {
    uint32_t a;
    asm("{ .reg .u64 t; cvta.to.shared.u64 t, %1; cvt.u32.u64 %0, t; }" : "=r"(a) : "l"(p));
    return a;
}
__device__ __forceinline__ void ldm_x4(uint32_t* r, uint32_t addr) {
    asm volatile("ldmatrix.sync.aligned.m8n8.x4.shared.b16 {%0,%1,%2,%3}, [%4];"
                 : "=r"(r[0]), "=r"(r[1]), "=r"(r[2]), "=r"(r[3]) : "r"(addr));
}
__device__ __forceinline__ void ldm_x2(uint32_t* r, uint32_t addr) {
    asm volatile("ldmatrix.sync.aligned.m8n8.x2.shared.b16 {%0,%1}, [%2];"
                 : "=r"(r[0]), "=r"(r[1]) : "r"(addr));
}
__device__ __forceinline__ void mma_bf16(float* c, const uint32_t* a, const uint32_t* b) {
    asm volatile("mma.sync.aligned.m16n8k16.row.col.f32.bf16.bf16.f32 "
                 "{%0,%1,%2,%3}, {%4,%5,%6,%7}, {%8,%9}, {%0,%1,%2,%3};"
                 : "+f"(c[0]), "+f"(c[1]), "+f"(c[2]), "+f"(c[3])
                 : "r"(a[0]), "r"(a[1]), "r"(a[2]), "r"(a[3]), "r"(b[0]), "r"(b[1]));
}

// ======================= 1. prep: fold + transpose + bf16 split ==================
__global__ __launch_bounds__(256) void prep_kernel(
    const float* __restrict__ Wk, const float* __restrict__ bk,
    const float* __restrict__ Wq, const float* __restrict__ bq,
    const float* __restrict__ Wv, const float* __restrict__ bv,
    const float* __restrict__ Wa,
    const float* __restrict__ w_att, const float* __restrict__ w_msg)
{
    const int t = blockIdx.y;
    const int n = blockIdx.x;
    const int k = threadIdx.x;

    float val;
    if (n < 768) {
        if (n < 256) {
            val = Wq[((size_t)t * 256 + k) * 256 + n];
        } else {
            const int j = (n - 256) & 255;
            const int h = j >> 5, jj = j & 31;
            const float* W = (n < 512) ? Wk : Wv;
            const float* wm = ((n < 512) ? w_att : w_msg) + ((size_t)(t * 8 + h)) * 1024 + jj;
            const float* wrow = W + ((size_t)t * 256 + k) * 256 + h * 32;
            float a = 0.f;
            #pragma unroll 8
            for (int i = 0; i < 32; ++i) a += wrow[i] * wm[i * 32];
            val = a;
        }
        __nv_bfloat16 hi = __float2bfloat16(val);
        __nv_bfloat16 lo = __float2bfloat16(val - __bfloat162float(hi));
        g_WcatT_hi[t][(size_t)n * 256 + k] = hi;
        g_WcatT_lo[t][(size_t)n * 256 + k] = lo;
        if (k == 0) {
            float b;
            if (n < 256) b = bq[t * 256 + n];
            else {
                const int j = (n - 256) & 255;
                const int h = j >> 5, jj = j & 31;
                const float* bb = (n < 512) ? bk : bv;
                const float* wm = ((n < 512) ? w_att : w_msg) + ((size_t)(t * 8 + h)) * 1024 + jj;
                float a = 0.f;
                #pragma unroll 8
                for (int i = 0; i < 32; ++i) a += bb[t * 256 + h * 32 + i] * wm[i * 32];
                b = a;
            }
            g_bcat[t][n] = b;
        }
    } else {
        const int nn = n - 768;
        val = Wa[((size_t)t * 256 + k) * 256 + nn];
        __nv_bfloat16 hi = __float2bfloat16(val);
        __nv_bfloat16 lo = __float2bfloat16(val - __bfloat162float(hi));
        g_WaT_hi[t][(size_t)nn * 256 + k] = hi;
        g_WaT_lo[t][(size_t)nn * 256 + k] = lo;
    }
}

// ======================= 2. fp32 -> bf16 hi/lo split =============================
__global__ void convsplit_kernel(const float* __restrict__ src,
                                 __nv_bfloat16* __restrict__ hi,
                                 __nv_bfloat16* __restrict__ lo, long n4)
{
    long i = (long)blockIdx.x * blockDim.x + threadIdx.x;
    if (i >= n4) return;
    float4 v = ((const float4*)src)[i];
    __nv_bfloat16 h0 = __float2bfloat16(v.x), h1 = __float2bfloat16(v.y);
    __nv_bfloat16 h2 = __float2bfloat16(v.z), h3 = __float2bfloat16(v.w);
    __nv_bfloat16 l0 = __float2bfloat16(v.x - __bfloat162float(h0));
    __nv_bfloat16 l1 = __float2bfloat16(v.y - __bfloat162float(h1));
    __nv_bfloat16 l2 = __float2bfloat16(v.z - __bfloat162float(h2));
    __nv_bfloat16 l3 = __float2bfloat16(v.w - __bfloat162float(h3));
    ((__nv_bfloat162*)hi)[i * 2]     = __halves2bfloat162(h0, h1);
    ((__nv_bfloat162*)hi)[i * 2 + 1] = __halves2bfloat162(h2, h3);
    ((__nv_bfloat162*)lo)[i * 2]     = __halves2bfloat162(l0, l1);
    ((__nv_bfloat162*)lo)[i * 2 + 1] = __halves2bfloat162(l2, l3);
}

// ======================= 3. CSR build: zero-deg, hist, scan, scatter =============
__global__ void zerodeg_kernel()
{
    int i = blockIdx.x * blockDim.x + threadIdx.x;
    if (i < 2 * NNODE) ((int*)g_deg)[i] = 0;
}

__global__ void hist_kernel(const int* __restrict__ dst)
{
    const int et = blockIdx.y;
    int e = blockIdx.x * blockDim.x + threadIdx.x;
    if (e >= EE) return;
    atomicAdd(&g_deg[et][dst[(long)et * EE + e]], 1);
}

// one block of 1024 threads per etype; two-pass chunked exclusive scan
__global__ __launch_bounds__(1024) void scan_kernel()
{
    const int et = blockIdx.x;
    const int t = threadIdx.x;
    const int CH = (NNODE + 1023) / 1024;   // 49
    const int start = t * CH;

    int sum = 0;
    for (int i = 0; i < CH; ++i) {
        int idx = start + i;
        if (idx < NNODE) sum += g_deg[et][idx];
    }
    // block scan of per-thread sums
    __shared__ int wsums[32];
    const int lane = t & 31, wid = t >> 5;
    int v = sum;
    #pragma unroll
    for (int o = 1; o < 32; o <<= 1) {
        int n = __shfl_up_sync(0xffffffffu, v, o);
        if (lane >= o) v += n;
    }
    if (lane == 31) wsums[wid] = v;
    __syncthreads();
    if (wid == 0) {
        int x = wsums[lane];
        #pragma unroll
        for (int o = 1; o < 32; o <<= 1) {
            int n = __shfl_up_sync(0xffffffffu, x, o);
            if (lane >= o) x += n;
        }
        wsums[lane] = x;
    }
    __syncthreads();
    int excl = v - sum + (wid > 0 ? wsums[wid - 1] : 0);

    int run = excl;
    for (int i = 0; i < CH; ++i) {
        int idx = start + i;
        if (idx < NNODE) {
            g_rows[et][idx] = run;
            g_cursor[et][idx] = run;
            run += g_deg[et][idx];
        }
    }
    if (t == 1023) g_rows[et][NNODE] = run;
}

__global__ void scatter_kernel(const int* __restrict__ src, const int* __restrict__ dst)
{
    const int et = blockIdx.y;
    int e = blockIdx.x * blockDim.x + threadIdx.x;
    if (e >= EE) return;
    int s = src[(long)et * EE + e];
    int d = dst[(long)et * EE + e];
    int pos = atomicAdd(&g_cursor[et][d], 1);
    g_esrc[et][pos] = s;
}

// ======================= 4. warp-per-dst aggregation ==============================
// For each dst node: q loaded once; loop over CSR edges gathering k/v; accumulate
// sum(w) and sum(w*v) in registers; normalize; emit bf16 hi/lo for GEMM2.
__global__ __launch_bounds__(256) void agg_kernel(const float* __restrict__ mu)
{
    const int et = blockIdx.y;
    const int dt = 1 - et;
    const int warp = threadIdx.x >> 5;
    const int lane = threadIdx.x & 31;
    const int node = blockIdx.x * 8 + warp;
    if (node >= NNODE) return;

    const int r0 = g_rows[et][node];
    const int r1 = g_rows[et][node + 1];

    const int h = lane >> 2;
    const int base = lane * 8;
    const float muh = mu[et * 8 + h] * ATT_SCALE;

    float4 qa, qb;
    float acc[8];
    #pragma unroll
    for (int j = 0; j < 8; ++j) acc[j] = 0.f;
    float wsum = 0.f;

    if (r0 < r1) {
        const float* qrow = g_QKV[dt] + (size_t)node * QKVW + base;
        qa = *(const float4*)qrow;
        qb = *(const float4*)(qrow + 4);

        const int* __restrict__ ep = g_esrc[et];
        int s_next = ep[r0];
        for (int j = r0; j < r1; ++j) {
            const int s = s_next;
            if (j + 1 < r1) s_next = ep[j + 1];
            const float* kr = g_QKV[et] + (size_t)s * QKVW + 256 + base;
            float4 ka = *(const float4*)kr;
            float4 kb = *(const float4*)(kr + 4);
            float4 va = *(const float4*)(kr + 256);
            float4 vb = *(const float4*)(kr + 260);

            float p = qa.x * ka.x + qa.y * ka.y + qa.z * ka.z + qa.w * ka.w
                    + qb.x * kb.x + qb.y * kb.y + qb.z * kb.z + qb.w * kb.w;
            p += __shfl_xor_sync(0xffffffffu, p, 1);
            p += __shfl_xor_sync(0xffffffffu, p, 2);

            float w = expf(p * muh);
            wsum += w;
            acc[0] += w * va.x;  acc[1] += w * va.y;
            acc[2] += w * va.z;  acc[3] += w * va.w;
            acc[4] += w * vb.x;  acc[5] += w * vb.y;
            acc[6] += w * vb.z;  acc[7] += w * vb.w;
        }
    }

    const float inv = (wsum > 0.f) ? 1.f / wsum : 0.f;
    __nv_bfloat162 hh[4], ll[4];
    #pragma unroll
    for (int j = 0; j < 4; ++j) {
        float x0 = acc[2 * j] * inv, x1 = acc[2 * j + 1] * inv;
        __nv_bfloat16 h0 = __float2bfloat16(x0), h1 = __float2bfloat16(x1);
        __nv_bfloat16 l0 = __float2bfloat16(x0 - __bfloat162float(h0));
        __nv_bfloat16 l1 = __float2bfloat16(x1 - __bfloat162float(h1));
        hh[j] = __halves2bfloat162(h0, h1);
        ll[j] = __halves2bfloat162(l0, l1);
    }
    const size_t o = (size_t)node * DDIM + base;
    *(uint4*)(g_hbf_hi[dt] + o) = *(const uint4*)hh;
    *(uint4*)(g_hbf_lo[dt] + o) = *(const uint4*)ll;
}

// ======================= 5. split-bf16 HMMA GEMM =================================
#define BM 128
#define BN 128
#define BK 64
#define LDS_STRIDE 72
#define AS_HI 0
#define AS_LO (AS_HI + BM * LDS_STRIDE * 2)
#define BS_HI (AS_LO + BM * LDS_STRIDE * 2)
#define BS_LO (BS_HI + BN * LDS_STRIDE * 2)
#define GEMM_SMEM (BS_LO + BN * LDS_STRIDE * 2)

__global__ __launch_bounds__(256) void hmma_gemm_kernel(
    const __nv_bfloat16* __restrict__ Ahi, const __nv_bfloat16* __restrict__ Alo, long strideA,
    const __nv_bfloat16* __restrict__ Bhi, const __nv_bfloat16* __restrict__ Blo, long strideB,
    const float* __restrict__ bias, long strideBias,
    float* __restrict__ C, long strideC,
    int M, int Ntot)
{
    extern __shared__ char smem[];
    const uint32_t sbase = smem_u32(smem);

    const int tid = threadIdx.x;
    const int wid = tid >> 5, lane = tid & 31;
    const int t = blockIdx.z;
    const int m0 = blockIdx.x * BM;
    const int n0 = blockIdx.y * BN;
    const int mw = (wid & 1) * 64;
    const int nw = (wid >> 1) * 32;

    Ahi += (size_t)t * strideA;  Alo += (size_t)t * strideA;
    Bhi += (size_t)t * strideB;  Blo += (size_t)t * strideB;
    bias += (size_t)t * strideBias;
    C += (size_t)t * strideC;

    float acc[4][4][4];
    #pragma unroll
    for (int i = 0; i < 4; ++i)
        #pragma unroll
        for (int j = 0; j < 4; ++j)
            #pragma unroll
            for (int r = 0; r < 4; ++r) acc[i][j][r] = 0.f;

    for (int kofs = 0; kofs < 256; kofs += BK) {
        __syncthreads();
        #pragma unroll
        for (int i = 0; i < 4; ++i) {
            int idx = tid + i * 256;
            int row = idx >> 3, c = (idx & 7) * 8;
            uint32_t soff = (uint32_t)(row * LDS_STRIDE + c) * 2;
            uint4 vh = make_uint4(0, 0, 0, 0), vl = make_uint4(0, 0, 0, 0);
            int gr = m0 + row;
            if (gr < M) {
                size_t s = (size_t)gr * 256 + kofs + c;
                vh = *(const uint4*)(Ahi + s);
                vl = *(const uint4*)(Alo + s);
            }
            *(uint4*)(smem + AS_HI + soff) = vh;
            *(uint4*)(smem + AS_LO + soff) = vl;
        }
        #pragma unroll
        for (int i = 0; i < 4; ++i) {
            int idx = tid + i * 256;
            int row = idx >> 3, c = (idx & 7) * 8;
            uint32_t soff = (uint32_t)(row * LDS_STRIDE + c) * 2;
            size_t s = (size_t)(n0 + row) * 256 + kofs + c;
            *(uint4*)(smem + BS_HI + soff) = *(const uint4*)(Bhi + s);
            *(uint4*)(smem + BS_LO + soff) = *(const uint4*)(Blo + s);
        }
        __syncthreads();

        #pragma unroll
        for (int kk = 0; kk < BK / 16; ++kk) {
            uint32_t a_hi[4][4], a_lo[4][4], b_hi[4][2], b_lo[4][2];
            #pragma unroll
            for (int i = 0; i < 4; ++i) {
                uint32_t off = (uint32_t)((mw + i * 16 + (lane & 15)) * LDS_STRIDE
                                          + kk * 16 + (lane >> 4) * 8) * 2;
                ldm_x4(a_hi[i], sbase + AS_HI + off);
                ldm_x4(a_lo[i], sbase + AS_LO + off);
            }
            #pragma unroll
            for (int j = 0; j < 4; ++j) {
                uint32_t off = (uint32_t)((nw + j * 8 + (lane & 7)) * LDS_STRIDE
                                          + kk * 16 + ((lane >> 3) & 1) * 8) * 2;
                ldm_x2(b_hi[j], sbase + BS_HI + off);
                ldm_x2(b_lo[j], sbase + BS_LO + off);
            }
            #pragma unroll
            for (int i = 0; i < 4; ++i)
                #pragma unroll
                for (int j = 0; j < 4; ++j) {
                    mma_bf16(acc[i][j], a_hi[i], b_hi[j]);
                    mma_bf16(acc[i][j], a_hi[i], b_lo[j]);
                    mma_bf16(acc[i][j], a_lo[i], b_hi[j]);
                }
        }
    }

    #pragma unroll
    for (int i = 0; i < 4; ++i) {
        int r0 = m0 + mw + i * 16 + (lane >> 2);
        int r1 = r0 + 8;
        #pragma unroll
        for (int j = 0; j < 4; ++j) {
            int col = n0 + nw + j * 8 + (lane & 3) * 2;
            float b0 = bias[col], b1 = bias[col + 1];
            if (r0 < M) {
                float2 o = make_float2(acc[i][j][0] + b0, acc[i][j][1] + b1);
                *(float2*)(C + (size_t)r0 * Ntot + col) = o;
            }
            if (r1 < M) {
                float2 o = make_float2(acc[i][j][2] + b0, acc[i][j][3] + b1);
                *(float2*)(C + (size_t)r1 * Ntot + col) = o;
            }
        }
    }
}

// ======================= 6. skip-mix + LayerNorm =================================
__global__ __launch_bounds__(256) void ln_kernel(
    const float* __restrict__ feats, const float* __restrict__ skip,
    const float* __restrict__ ln_w, const float* __restrict__ ln_b,
    float* __restrict__ out)
{
    long row = (long)blockIdx.x * 8 + (threadIdx.x >> 5);
    const int lane = threadIdx.x & 31;
    const int t = (int)(row / NNODE);
    const float alpha = 1.f / (1.f + expf(-skip[t]));
    const float beta = 1.f - alpha;

    const float* tr = (const float*)g_trans + row * DDIM + lane * 8;
    const float* ft = feats + row * DDIM + lane * 8;

    float v[8];
    float4 t0 = *(const float4*)(tr);
    float4 t1 = *(const float4*)(tr + 4);
    float4 f0 = *(const float4*)(ft);
    float4 f1 = *(const float4*)(ft + 4);
    v[0] = alpha * t0.x + beta * f0.x;  v[1] = alpha * t0.y + beta * f0.y;
    v[2] = alpha * t0.z + beta * f0.z;  v[3] = alpha * t0.w + beta * f0.w;
    v[4] = alpha * t1.x + beta * f1.x;  v[5] = alpha * t1.y + beta * f1.y;
    v[6] = alpha * t1.z + beta * f1.z;  v[7] = alpha * t1.w + beta * f1.w;

    float sum = 0.f, sq = 0.f;
    #pragma unroll
    for (int j = 0; j < 8; ++j) { sum += v[j]; sq += v[j] * v[j]; }
    #pragma unroll
    for (int o = 16; o > 0; o >>= 1) {
        sum += __shfl_xor_sync(0xffffffffu, sum, o);
        sq  += __shfl_xor_sync(0xffffffffu, sq, o);
    }
    const float mean = sum * (1.f / 256.f);
    const float var  = sq * (1.f / 256.f) - mean * mean;
    const float rstd = rsqrtf(var + 1e-5f);

    const int cbase = t * 256 + lane * 8;
    float* op = out + row * DDIM + lane * 8;
    float4 o0, o1;
    o0.x = (v[0] - mean) * rstd * ln_w[cbase + 0] + ln_b[cbase + 0];
    o0.y = (v[1] - mean) * rstd * ln_w[cbase + 1] + ln_b[cbase + 1];
    o0.z = (v[2] - mean) * rstd * ln_w[cbase + 2] + ln_b[cbase + 2];
    o0.w = (v[3] - mean) * rstd * ln_w[cbase + 3] + ln_b[cbase + 3];
    o1.x = (v[4] - mean) * rstd * ln_w[cbase + 4] + ln_b[cbase + 4];
    o1.y = (v[5] - mean) * rstd * ln_w[cbase + 5] + ln_b[cbase + 5];
    o1.z = (v[6] - mean) * rstd * ln_w[cbase + 6] + ln_b[cbase + 6];
    o1.w = (v[7] - mean) * rstd * ln_w[cbase + 7] + ln_b[cbase + 7];
    *(float4*)(op)     = o0;
    *(float4*)(op + 4) = o1;
}

// ======================= host launch =============================================
extern "C" void kernel_launch(void* const* d_in, const int* in_sizes, int n_in,
                              void* d_out, int out_size)
{
    const float* feats = (const float*)d_in[0];
    const float* Wk    = (const float*)d_in[1];
    const float* bk    = (const float*)d_in[2];
    const float* Wq    = (const float*)d_in[3];
    const float* bq    = (const float*)d_in[4];
    const float* Wv    = (const float*)d_in[5];
    const float* bv    = (const float*)d_in[6];
    const float* Wa    = (const float*)d_in[7];
    const float* ba    = (const float*)d_in[8];
    const float* ln_w  = (const float*)d_in[9];
    const float* ln_b  = (const float*)d_in[10];
    const float* skip  = (const float*)d_in[11];
    const float* mu    = (const float*)d_in[12];
    const float* w_att = (const float*)d_in[13];
    const float* w_msg = (const float*)d_in[14];
    const int*   src   = (const int*)d_in[15];
    const int*   dst   = (const int*)d_in[16];
    float* out = (float*)d_out;

    static bool attr_done = false;
    if (!attr_done) {
        cudaFuncSetAttribute(hmma_gemm_kernel,
                             cudaFuncAttributeMaxDynamicSharedMemorySize, GEMM_SMEM);
        attr_done = true;
    }

    float *pbcat, *pQKV, *ptrans;
    __nv_bfloat16 *pWcH, *pWcL, *pWaH, *pWaL, *pfH, *pfL, *phH, *phL;
    cudaGetSymbolAddress((void**)&pbcat, g_bcat);
    cudaGetSymbolAddress((void**)&pQKV, g_QKV);
    cudaGetSymbolAddress((void**)&ptrans, g_trans);
    cudaGetSymbolAddress((void**)&pWcH, g_WcatT_hi);
    cudaGetSymbolAddress((void**)&pWcL, g_WcatT_lo);
    cudaGetSymbolAddress((void**)&pWaH, g_WaT_hi);
    cudaGetSymbolAddress((void**)&pWaL, g_WaT_lo);
    cudaGetSymbolAddress((void**)&pfH, g_fbf_hi);
    cudaGetSymbolAddress((void**)&pfL, g_fbf_lo);
    cudaGetSymbolAddress((void**)&phH, g_hbf_hi);
    cudaGetSymbolAddress((void**)&phL, g_hbf_lo);

    // 1. weight prep
    {
        dim3 grid(1024, 2);
        prep_kernel<<<grid, 256>>>(Wk, bk, Wq, bq, Wv, bv, Wa, w_att, w_msg);
    }

    // 2. feats -> bf16 hi/lo
    {
        const long n4 = 2L * NNODE * DDIM / 4;
        convsplit_kernel<<<(int)((n4 + 255) / 256), 256>>>(feats, pfH, pfL, n4);
    }

    // 3. CSR build (overlaps QKV GEMM dependency-wise; stream is serial but cheap)
    zerodeg_kernel<<<(2 * NNODE + 255) / 256, 256>>>();
    {
        dim3 grid((EE + 255) / 256, 2);
        hist_kernel<<<grid, 256>>>(dst);
    }
    scan_kernel<<<2, 1024>>>();
    {
        dim3 grid((EE + 255) / 256, 2);
        scatter_kernel<<<grid, 256>>>(src, dst);
    }

    // 4. QKV projection (HMMA)
    {
        dim3 grid((NNODE + BM - 1) / BM, QKVW / BN, 2);
        hmma_gemm_kernel<<<grid, 256, GEMM_SMEM>>>(
            pfH, pfL, (long)NNODE * DDIM,
            pWcH, pWcL, (long)QKVW * DDIM,
            pbcat, (long)QKVW,
            pQKV, (long)NNODE * QKVW,
            NNODE, QKVW);
    }

    // 5. aggregation (scores + softmax + weighted sum + bf16 split, fused)
    {
        dim3 grid((NNODE + 7) / 8, 2);
        agg_kernel<<<grid, 256>>>(mu);
    }

    // 6. output projection (HMMA)
    {
        dim3 grid((NNODE + BM - 1) / BM, DDIM / BN, 2);
        hmma_gemm_kernel<<<grid, 256, GEMM_SMEM>>>(
            phH, phL, (long)NNODE * DDIM,
            pWaH, pWaL, (long)DDIM * DDIM,
            ba, (long)DDIM,
            ptrans, (long)NNODE * DDIM,
            NNODE, DDIM);
    }

    // 7. skip-mix + LayerNorm -> d_out
    ln_kernel<<<(2 * NNODE) / 8, 256>>>(feats, skip, ln_w, ln_b, out);
}